// round 2
// baseline (speedup 1.0000x reference)
#include <cuda_runtime.h>
#include <math.h>

// ---------------------------------------------------------------------------
// MultiHeadDiffAttention  (B=4, T=1024, C=1024, H=16, hs=64, dv=128)
//   y = softmax(q1 k1^T) v  -  lam_h * softmax(q2 k2^T) v   (causal)
//   then subLN over 128, * (1-lambda_init), then @ Wc
// ---------------------------------------------------------------------------

#define BTROWS 4096          // B*T
static __device__ float g_q1[4096 * 1024];
static __device__ float g_q2[4096 * 1024];
static __device__ float g_k1[4096 * 1024];
static __device__ float g_k2[4096 * 1024];
static __device__ float g_v [4096 * 2048];
static __device__ float g_y1[4096 * 2048];
static __device__ float g_y2[4096 * 2048];
static __device__ float g_yc[4096 * 2048];

#define LAMBDA_INIT 0.3555090675909693f   // 0.8 - 0.6*exp(-0.3)

// ---------------------------------------------------------------------------
// SGEMM: C[M,N] = A[M,K] @ B[K,N], all row-major fp32.
// BM=BN=128, BK=8, TM=TN=8, 256 threads. M%128==0, N%128==0, K%8==0 assumed.
// ---------------------------------------------------------------------------
__global__ __launch_bounds__(256) void sgemm_kernel(
    const float* __restrict__ A, const float* __restrict__ B,
    float* __restrict__ C, int M, int N, int K)
{
    const int BM = 128, BN = 128, BK = 8, TM = 8, TN = 8;
    __shared__ float As[BK * BM];   // stored transposed: As[k][m]
    __shared__ float Bs[BK * BN];

    const int tid = threadIdx.x;
    const int threadCol = tid % (BN / TN);   // 0..15
    const int threadRow = tid / (BN / TN);   // 0..15

    const int innerRowA = tid / (BK / 4);    // 0..127
    const int innerColA = tid % (BK / 4);    // 0..1
    const int innerRowB = tid / (BN / 4);    // 0..7
    const int innerColB = tid % (BN / 4);    // 0..31

    A += (size_t)blockIdx.y * BM * K;
    B += (size_t)blockIdx.x * BN;
    C += (size_t)blockIdx.y * BM * N + (size_t)blockIdx.x * BN;

    float acc[TM][TN];
#pragma unroll
    for (int i = 0; i < TM; i++)
#pragma unroll
        for (int j = 0; j < TN; j++) acc[i][j] = 0.f;

    float regM[TM], regN[TN];

    for (int k0 = 0; k0 < K; k0 += BK) {
        float4 a = *(const float4*)(&A[(size_t)innerRowA * K + innerColA * 4]);
        As[(innerColA * 4 + 0) * BM + innerRowA] = a.x;
        As[(innerColA * 4 + 1) * BM + innerRowA] = a.y;
        As[(innerColA * 4 + 2) * BM + innerRowA] = a.z;
        As[(innerColA * 4 + 3) * BM + innerRowA] = a.w;
        *(float4*)(&Bs[innerRowB * BN + innerColB * 4]) =
            *(const float4*)(&B[(size_t)innerRowB * N + innerColB * 4]);
        __syncthreads();
        A += BK;
        B += (size_t)BK * N;
#pragma unroll
        for (int k = 0; k < BK; k++) {
#pragma unroll
            for (int i = 0; i < TM; i += 4)
                *(float4*)(&regM[i]) = *(const float4*)(&As[k * BM + threadRow * TM + i]);
#pragma unroll
            for (int j = 0; j < TN; j += 4)
                *(float4*)(&regN[j]) = *(const float4*)(&Bs[k * BN + threadCol * TN + j]);
#pragma unroll
            for (int i = 0; i < TM; i++)
#pragma unroll
                for (int j = 0; j < TN; j++) acc[i][j] += regM[i] * regN[j];
        }
        __syncthreads();
    }
#pragma unroll
    for (int i = 0; i < TM; i++)
#pragma unroll
        for (int j = 0; j < TN; j += 4) {
            float4 t = make_float4(acc[i][j], acc[i][j + 1], acc[i][j + 2], acc[i][j + 3]);
            *(float4*)(&C[(size_t)(threadRow * TM + i) * N + threadCol * TN + j]) = t;
        }
}

// ---------------------------------------------------------------------------
// Causal flash attention, one softmax stream.
// Q,K: (4096, 1024) row-major; head h at cols [h*64, h*64+64)
// V:   (4096, 2048); head h at cols [h*128, h*128+128)
// O:   (4096, 2048); head h at cols [h*128, h*128+128)
// grid (T/32, H, B), block 128.
// ---------------------------------------------------------------------------
__global__ __launch_bounds__(128) void flash_kernel(
    const float* __restrict__ Q, const float* __restrict__ K,
    const float* __restrict__ V, float* __restrict__ O)
{
    __shared__ float sQ[32][68];     // Q tile, row-major, padded
    __shared__ float sKt[64][36];    // K tile transposed [k-dim][row], padded
    __shared__ float sV[32][128];    // V tile
    __shared__ float sS[32][33];     // scores / probs, padded

    const int qt = blockIdx.x, h = blockIdx.y, b = blockIdx.z;
    const int tid = threadIdx.x;
    const int q0 = qt * 32;

    const float* Qb = Q + (size_t)(b * 1024 + q0) * 1024 + h * 64;
    const float* Kb = K + (size_t)(b * 1024) * 1024 + h * 64;
    const float* Vb = V + (size_t)(b * 1024) * 2048 + h * 128;

    // load Q tile: 32x64 floats = 512 float4
    for (int i = tid; i < 512; i += 128) {
        int r = i >> 4, c4 = i & 15;
        *(float4*)(&sQ[r][c4 * 4]) = *(const float4*)(Qb + (size_t)r * 1024 + c4 * 4);
    }

    const int row = tid >> 2;   // 0..31
    const int cg  = tid & 3;    // 0..3 (column group for PV / output)

    float acc[8][4];
#pragma unroll
    for (int i = 0; i < 8; i++)
#pragma unroll
        for (int j = 0; j < 4; j++) acc[i][j] = 0.f;
    float m = -INFINITY, l = 0.f;

    for (int kt = 0; kt <= qt; kt++) {
        __syncthreads();   // previous iteration's reads of sKt/sV/sS done
        const int kbase = kt * 32;
        // K 32x64 -> transposed smem
        for (int i = tid; i < 512; i += 128) {
            int r = i >> 4, c4 = i & 15;
            float4 t = *(const float4*)(Kb + (size_t)(kbase + r) * 1024 + c4 * 4);
            sKt[c4 * 4 + 0][r] = t.x;
            sKt[c4 * 4 + 1][r] = t.y;
            sKt[c4 * 4 + 2][r] = t.z;
            sKt[c4 * 4 + 3][r] = t.w;
        }
        // V 32x128
        for (int i = tid; i < 1024; i += 128) {
            int r = i >> 5, c4 = i & 31;
            *(float4*)(&sV[r][c4 * 4]) = *(const float4*)(Vb + (size_t)(kbase + r) * 2048 + c4 * 4);
        }
        __syncthreads();

        // S = (Q K^T) * scale with causal mask. Thread microtile: 2 rows x 4 cols.
        {
            const int rg = tid >> 3;      // 0..15 -> rows rg*2, rg*2+1
            const int cgc = tid & 7;      // 0..7  -> cols cgc*4..+3
            float s00 = 0, s01 = 0, s02 = 0, s03 = 0;
            float s10 = 0, s11 = 0, s12 = 0, s13 = 0;
#pragma unroll 8
            for (int kk = 0; kk < 64; kk++) {
                float qa = sQ[rg * 2 + 0][kk];
                float qb = sQ[rg * 2 + 1][kk];
                float4 kv = *(const float4*)(&sKt[kk][cgc * 4]);
                s00 += qa * kv.x; s01 += qa * kv.y; s02 += qa * kv.z; s03 += qa * kv.w;
                s10 += qb * kv.x; s11 += qb * kv.y; s12 += qb * kv.z; s13 += qb * kv.w;
            }
            const float sc = 0.125f;   // 1/sqrt(64)
            float vals[2][4] = {{s00, s01, s02, s03}, {s10, s11, s12, s13}};
#pragma unroll
            for (int i = 0; i < 2; i++)
#pragma unroll
                for (int j = 0; j < 4; j++) {
                    int gr = q0 + rg * 2 + i;
                    int gc = kbase + cgc * 4 + j;
                    sS[rg * 2 + i][cgc * 4 + j] = (gc <= gr) ? vals[i][j] * sc : -INFINITY;
                }
        }
        __syncthreads();

        // online softmax (4 threads per row redundantly compute the row stats)
        float tmax = -INFINITY;
#pragma unroll
        for (int j = 0; j < 32; j++) tmax = fmaxf(tmax, sS[row][j]);
        float mnew = fmaxf(m, tmax);
        float alpha = __expf(m - mnew);   // first iter: exp(-inf)=0
        __syncthreads();                  // all max-reads done before exp-writes
#pragma unroll
        for (int j = cg; j < 32; j += 4)
            sS[row][j] = __expf(sS[row][j] - mnew);
        __syncthreads();
        float rowsum = 0.f;
#pragma unroll
        for (int j = 0; j < 32; j++) rowsum += sS[row][j];
        l = alpha * l + rowsum;
        m = mnew;
#pragma unroll
        for (int i = 0; i < 8; i++) {
            acc[i][0] *= alpha; acc[i][1] *= alpha;
            acc[i][2] *= alpha; acc[i][3] *= alpha;
        }
        // O += P @ V ; this thread owns v-cols (cg + ii*4)*4 .. +3, ii=0..7
        for (int j = 0; j < 32; j++) {
            float p = sS[row][j];
#pragma unroll
            for (int ii = 0; ii < 8; ii++) {
                float4 vv = *(const float4*)(&sV[j][(cg + ii * 4) * 4]);
                acc[ii][0] += p * vv.x; acc[ii][1] += p * vv.y;
                acc[ii][2] += p * vv.z; acc[ii][3] += p * vv.w;
            }
        }
    }

    float inv = 1.f / l;
    float* Ob = O + (size_t)(b * 1024 + q0 + row) * 2048 + h * 128;
#pragma unroll
    for (int ii = 0; ii < 8; ii++) {
        float4 t = make_float4(acc[ii][0] * inv, acc[ii][1] * inv,
                               acc[ii][2] * inv, acc[ii][3] * inv);
        *(float4*)(Ob + (cg + ii * 4) * 4) = t;
    }
}

// ---------------------------------------------------------------------------
// Combine: z = y1 - lam_h*y2, subLN over 128, * (1-lambda_init).
// grid 4096 (rows), block 512 = 16 warps (one per head).
// ---------------------------------------------------------------------------
__global__ __launch_bounds__(512) void combine_kernel(
    const float* __restrict__ y1, const float* __restrict__ y2,
    const float* __restrict__ lq1, const float* __restrict__ lk1,
    const float* __restrict__ lq2, const float* __restrict__ lk2,
    float* __restrict__ out)
{
    const int rowidx = blockIdx.x;
    const int h = threadIdx.x >> 5;
    const int lane = threadIdx.x & 31;

    // per-head lambda
    float s1 = lq1[h * 64 + lane] * lk1[h * 64 + lane]
             + lq1[h * 64 + 32 + lane] * lk1[h * 64 + 32 + lane];
    float s2 = lq2[h * 64 + lane] * lk2[h * 64 + lane]
             + lq2[h * 64 + 32 + lane] * lk2[h * 64 + 32 + lane];
#pragma unroll
    for (int o = 16; o > 0; o >>= 1) {
        s1 += __shfl_xor_sync(0xFFFFFFFFu, s1, o);
        s2 += __shfl_xor_sync(0xFFFFFFFFu, s2, o);
    }
    const float lam = __expf(s1) - __expf(s2) + LAMBDA_INIT;

    const size_t base = (size_t)rowidx * 2048 + h * 128 + lane * 4;
    float4 a = *(const float4*)(y1 + base);
    float4 b = *(const float4*)(y2 + base);
    float z0 = a.x - lam * b.x, z1 = a.y - lam * b.y;
    float z2 = a.z - lam * b.z, z3 = a.w - lam * b.w;

    float ssum = z0 + z1 + z2 + z3;
#pragma unroll
    for (int o = 16; o > 0; o >>= 1) ssum += __shfl_xor_sync(0xFFFFFFFFu, ssum, o);
    const float mu = ssum * (1.f / 128.f);

    float d0 = z0 - mu, d1 = z1 - mu, d2 = z2 - mu, d3 = z3 - mu;
    float vs = d0 * d0 + d1 * d1 + d2 * d2 + d3 * d3;
#pragma unroll
    for (int o = 16; o > 0; o >>= 1) vs += __shfl_xor_sync(0xFFFFFFFFu, vs, o);
    const float var = vs * (1.f / 128.f);

    const float r = rsqrtf(var + 1e-5f) * (1.f - LAMBDA_INIT);
    float4 o4 = make_float4(d0 * r, d1 * r, d2 * r, d3 * r);
    *(float4*)(out + base) = o4;
}

// ---------------------------------------------------------------------------
extern "C" void kernel_launch(void* const* d_in, const int* in_sizes, int n_in,
                              void* d_out, int out_size)
{
    const float* x   = (const float*)d_in[0];
    const float* Wq1 = (const float*)d_in[1];
    const float* Wq2 = (const float*)d_in[2];
    const float* Wk1 = (const float*)d_in[3];
    const float* Wk2 = (const float*)d_in[4];
    const float* Wv  = (const float*)d_in[5];
    const float* Wc  = (const float*)d_in[6];
    const float* lq1 = (const float*)d_in[7];
    const float* lk1 = (const float*)d_in[8];
    const float* lq2 = (const float*)d_in[9];
    const float* lk2 = (const float*)d_in[10];

    float *q1, *q2, *k1, *k2, *v, *y1, *y2, *yc;
    cudaGetSymbolAddress((void**)&q1, g_q1);
    cudaGetSymbolAddress((void**)&q2, g_q2);
    cudaGetSymbolAddress((void**)&k1, g_k1);
    cudaGetSymbolAddress((void**)&k2, g_k2);
    cudaGetSymbolAddress((void**)&v,  g_v);
    cudaGetSymbolAddress((void**)&y1, g_y1);
    cudaGetSymbolAddress((void**)&y2, g_y2);
    cudaGetSymbolAddress((void**)&yc, g_yc);

    // projections
    dim3 gP(1024 / 128, 4096 / 128);   // (8, 32)
    sgemm_kernel<<<gP, 256>>>(x, Wq1, q1, 4096, 1024, 1024);
    sgemm_kernel<<<gP, 256>>>(x, Wq2, q2, 4096, 1024, 1024);
    sgemm_kernel<<<gP, 256>>>(x, Wk1, k1, 4096, 1024, 1024);
    sgemm_kernel<<<gP, 256>>>(x, Wk2, k2, 4096, 1024, 1024);
    sgemm_kernel<<<dim3(2048 / 128, 4096 / 128), 256>>>(x, Wv, v, 4096, 2048, 1024);

    // dual flash attention streams
    dim3 gF(1024 / 32, 16, 4);
    flash_kernel<<<gF, 128>>>(q1, k1, v, y1);
    flash_kernel<<<gF, 128>>>(q2, k2, v, y2);

    // combine + subLN
    combine_kernel<<<4096, 512>>>(y1, y2, lq1, lk1, lq2, lk2, yc);

    // output projection
    sgemm_kernel<<<dim3(1024 / 128, 4096 / 128), 256>>>(yc, Wc, (float*)d_out,
                                                        4096, 1024, 2048);
}

// round 4
// speedup vs baseline: 1.4343x; 1.4343x over previous
#include <cuda_runtime.h>
#include <cuda_bf16.h>
#include <stdint.h>
#include <math.h>

// ---------------------------------------------------------------------------
// MultiHeadDiffAttention  (B=4, T=1024, C=1024, H=16, hs=64, dv=128)
//   y = softmax(q1 k1^T) v  -  lam_h * softmax(q2 k2^T) v   (causal)
//   then subLN over 128, * (1-lambda_init), then @ Wc
//
// R3: all 6 GEMMs via mma.sync bf16 split-precision (Ah*Bh + Ah*Bl + Al*Bh,
//     fp32 accumulate). No tcgen05 (harness PTX pass targets plain sm_103).
// ---------------------------------------------------------------------------

#define LAMBDA_INIT 0.3555090675909693f   // 0.8 - 0.6*exp(-0.3)

// fp32 intermediates
static __device__ float g_q1[4096 * 1024];
static __device__ float g_q2[4096 * 1024];
static __device__ float g_k1[4096 * 1024];
static __device__ float g_k2[4096 * 1024];
static __device__ float g_v [4096 * 2048];
static __device__ float g_y1[4096 * 2048];
static __device__ float g_y2[4096 * 2048];
static __device__ float g_yc[4096 * 2048];

// bf16 split buffers (activations [M,K]; weights transposed to [N,K])
static __device__ __align__(16) __nv_bfloat16 g_xh[4096 * 1024];
static __device__ __align__(16) __nv_bfloat16 g_xl[4096 * 1024];
static __device__ __align__(16) __nv_bfloat16 g_ych[4096 * 2048];
static __device__ __align__(16) __nv_bfloat16 g_ycl[4096 * 2048];
static __device__ __align__(16) __nv_bfloat16 g_w1h[1024 * 1024], g_w1l[1024 * 1024];
static __device__ __align__(16) __nv_bfloat16 g_w2h[1024 * 1024], g_w2l[1024 * 1024];
static __device__ __align__(16) __nv_bfloat16 g_w3h[1024 * 1024], g_w3l[1024 * 1024];
static __device__ __align__(16) __nv_bfloat16 g_w4h[1024 * 1024], g_w4l[1024 * 1024];
static __device__ __align__(16) __nv_bfloat16 g_wvh[2048 * 1024], g_wvl[2048 * 1024];
static __device__ __align__(16) __nv_bfloat16 g_wch[1024 * 2048], g_wcl[1024 * 2048];

// ---------------------------------------------------------------------------
// helpers
// ---------------------------------------------------------------------------
__device__ __forceinline__ uint32_t smem_u32(const void* p) {
    uint32_t a;
    asm("{ .reg .u64 t; cvta.to.shared.u64 t, %1; cvt.u32.u64 %0, t; }" : "=r"(a) : "l"(p));
    return a;
}
__device__ __forceinline__ void cp16(uint32_t saddr, const void* g) {
    asm volatile("cp.async.cg.shared.global [%0], [%1], 16;" :: "r"(saddr), "l"(g) : "memory");
}
__device__ __forceinline__ void cp_commit() {
    asm volatile("cp.async.commit_group;" ::: "memory");
}
__device__ __forceinline__ void ldsm4(uint32_t* r, uint32_t addr) {
    asm volatile("ldmatrix.sync.aligned.m8n8.x4.shared.b16 {%0,%1,%2,%3}, [%4];"
                 : "=r"(r[0]), "=r"(r[1]), "=r"(r[2]), "=r"(r[3]) : "r"(addr));
}
__device__ __forceinline__ void mma_bf16(float* d, const uint32_t* a, const uint32_t* b) {
    asm volatile(
        "mma.sync.aligned.m16n8k16.row.col.f32.bf16.bf16.f32 "
        "{%0,%1,%2,%3}, {%4,%5,%6,%7}, {%8,%9}, {%0,%1,%2,%3};"
        : "+f"(d[0]), "+f"(d[1]), "+f"(d[2]), "+f"(d[3])
        : "r"(a[0]), "r"(a[1]), "r"(a[2]), "r"(a[3]), "r"(b[0]), "r"(b[1]));
}

// ---------------------------------------------------------------------------
// Split-bf16 tensor-core GEMM: C[M,N] fp32 = A[M,K] @ B[N,K]^T
//   A = Ah + Al (bf16, row-major [M,K]); B = Bh + Bl (bf16, row-major [N,K])
//   C += via 3 HMMA terms: Ah*Bh + Ah*Bl + Al*Bh
// BM=BN=128, BK=32, 256 threads (8 warps: 2 m x 4 n, warp tile 64x32),
// 3-stage cp.async pipeline, xor-swizzled smem for conflict-free ldmatrix.
// ---------------------------------------------------------------------------
#define GBM 128
#define GBN 128
#define GBK 32
#define GTILE_B (GBM * GBK * 2)       // 8192 bytes per matrix tile
#define GSTAGE_B (4 * GTILE_B)        // Ah, Al, Bh, Bl
#define GSTAGES 3
#define GSMEM (GSTAGES * GSTAGE_B)    // 98304

__global__ __launch_bounds__(256, 1) void gemm_mma_kernel(
    const __nv_bfloat16* __restrict__ Ah, const __nv_bfloat16* __restrict__ Al,
    const __nv_bfloat16* __restrict__ Bh, const __nv_bfloat16* __restrict__ Bl,
    float* __restrict__ C, int K, int N)
{
    extern __shared__ char smem[];
    const uint32_t sb = smem_u32(smem);
    const int tid = threadIdx.x;
    const int wid = tid >> 5, lane = tid & 31;
    const int m0 = blockIdx.y * GBM, n0 = blockIdx.x * GBN;
    const int wm = (wid & 1) * 64, wn = (wid >> 1) * 32;
    const int nk = K / GBK;

    float acc[4][4][4];
#pragma unroll
    for (int i = 0; i < 4; i++)
#pragma unroll
        for (int j = 0; j < 4; j++)
#pragma unroll
            for (int r = 0; r < 4; r++) acc[i][j][r] = 0.f;

    // each thread loads 2 16B chunks per tile; chunk ch: row=ch>>2, c=ch&3
    const int ch0_row = tid >> 2, ch0_c = tid & 3;
    const int ch1_row = (tid + 256) >> 2, ch1_c = tid & 3;   // +256 => row+64, same c
    const uint32_t so0 = ch0_row * 64 + ((ch0_c ^ ((ch0_row >> 1) & 3)) * 16);
    const uint32_t so1 = ch1_row * 64 + ((ch1_c ^ ((ch1_row >> 1) & 3)) * 16);

#define LOAD_STAGE(kt, s)                                                          \
    do {                                                                           \
        const uint32_t sbase = sb + (s) * GSTAGE_B;                                \
        const int k0 = (kt) * GBK;                                                 \
        cp16(sbase + 0 * GTILE_B + so0, Ah + (size_t)(m0 + ch0_row) * K + k0 + ch0_c * 8); \
        cp16(sbase + 0 * GTILE_B + so1, Ah + (size_t)(m0 + ch1_row) * K + k0 + ch1_c * 8); \
        cp16(sbase + 1 * GTILE_B + so0, Al + (size_t)(m0 + ch0_row) * K + k0 + ch0_c * 8); \
        cp16(sbase + 1 * GTILE_B + so1, Al + (size_t)(m0 + ch1_row) * K + k0 + ch1_c * 8); \
        cp16(sbase + 2 * GTILE_B + so0, Bh + (size_t)(n0 + ch0_row) * K + k0 + ch0_c * 8); \
        cp16(sbase + 2 * GTILE_B + so1, Bh + (size_t)(n0 + ch1_row) * K + k0 + ch1_c * 8); \
        cp16(sbase + 3 * GTILE_B + so0, Bl + (size_t)(n0 + ch0_row) * K + k0 + ch0_c * 8); \
        cp16(sbase + 3 * GTILE_B + so1, Bl + (size_t)(n0 + ch1_row) * K + k0 + ch1_c * 8); \
    } while (0)

    LOAD_STAGE(0, 0); cp_commit();
    LOAD_STAGE(1, 1); cp_commit();

    // ldmatrix per-thread offsets (row part fixed per thread)
    const int a_row_in_tile = lane & 15;                         // + tm*16 + wm
    const int a_chunk_add   = lane >> 4;                         // 0/1
    const int b_row_in_tile = (lane & 7) + ((lane >> 4) << 3);   // + tn*16 + wn
    const int b_chunk_add   = (lane >> 3) & 1;

    int stage = 0;
    for (int kt = 0; kt < nk; kt++) {
        if (kt + 2 < nk) LOAD_STAGE(kt + 2, (kt + 2) % GSTAGES);
        cp_commit();
        asm volatile("cp.async.wait_group 2;" ::: "memory");
        __syncthreads();

        const uint32_t sA_h = sb + stage * GSTAGE_B;
        const uint32_t sA_l = sA_h + GTILE_B;
        const uint32_t sB_h = sA_h + 2 * GTILE_B;
        const uint32_t sB_l = sA_h + 3 * GTILE_B;

#pragma unroll
        for (int ks = 0; ks < 2; ks++) {
            uint32_t ah[4][4], al[4][4], bh[2][4], bl[2][4];
#pragma unroll
            for (int tm = 0; tm < 4; tm++) {
                const int row = wm + tm * 16 + a_row_in_tile;
                const int chunk = ks * 2 + a_chunk_add;
                const uint32_t off = row * 64 + ((chunk ^ ((row >> 1) & 3)) * 16);
                ldsm4(ah[tm], sA_h + off);
                ldsm4(al[tm], sA_l + off);
            }
#pragma unroll
            for (int tp = 0; tp < 2; tp++) {
                const int row = wn + tp * 16 + b_row_in_tile;
                const int chunk = ks * 2 + b_chunk_add;
                const uint32_t off = row * 64 + ((chunk ^ ((row >> 1) & 3)) * 16);
                ldsm4(bh[tp], sB_h + off);
                ldsm4(bl[tp], sB_l + off);
            }
#pragma unroll
            for (int tm = 0; tm < 4; tm++)
#pragma unroll
                for (int tn = 0; tn < 4; tn++) {
                    const int p = tn >> 1, hh = (tn & 1) * 2;
                    mma_bf16(acc[tm][tn], ah[tm], &bh[p][hh]);
                    mma_bf16(acc[tm][tn], ah[tm], &bl[p][hh]);
                    mma_bf16(acc[tm][tn], al[tm], &bh[p][hh]);
                }
        }
        __syncthreads();
        stage = (stage + 1) % GSTAGES;
    }

    // epilogue
    const int g = lane >> 2, cq = lane & 3;
#pragma unroll
    for (int tm = 0; tm < 4; tm++)
#pragma unroll
        for (int tn = 0; tn < 4; tn++) {
            const int row = m0 + wm + tm * 16 + g;
            const int col = n0 + wn + tn * 8 + cq * 2;
            *(float2*)&C[(size_t)row * N + col] = make_float2(acc[tm][tn][0], acc[tm][tn][1]);
            *(float2*)&C[(size_t)(row + 8) * N + col] = make_float2(acc[tm][tn][2], acc[tm][tn][3]);
        }
#undef LOAD_STAGE
}

// ---------------------------------------------------------------------------
// fp32 -> (hi, lo) bf16 split, contiguous
// ---------------------------------------------------------------------------
__global__ __launch_bounds__(256) void split_kernel(
    const float4* __restrict__ in, __nv_bfloat16* __restrict__ hi,
    __nv_bfloat16* __restrict__ lo, int n4)
{
    int i = blockIdx.x * blockDim.x + threadIdx.x;
    if (i >= n4) return;
    float4 v = in[i];
    __nv_bfloat16 h0 = __float2bfloat16(v.x), h1 = __float2bfloat16(v.y);
    __nv_bfloat16 h2 = __float2bfloat16(v.z), h3 = __float2bfloat16(v.w);
    __nv_bfloat162* H = (__nv_bfloat162*)hi + 2 * i;
    __nv_bfloat162* L = (__nv_bfloat162*)lo + 2 * i;
    H[0] = __nv_bfloat162(h0, h1);
    H[1] = __nv_bfloat162(h2, h3);
    L[0] = __nv_bfloat162(__float2bfloat16(v.x - __bfloat162float(h0)),
                          __float2bfloat16(v.y - __bfloat162float(h1)));
    L[1] = __nv_bfloat162(__float2bfloat16(v.z - __bfloat162float(h2)),
                          __float2bfloat16(v.w - __bfloat162float(h3)));
}

// ---------------------------------------------------------------------------
// fp32 [K,N] -> transposed (hi, lo) bf16 [N,K]; grid (N/32, K/32), block (32,8)
// ---------------------------------------------------------------------------
__global__ __launch_bounds__(256) void splitT_kernel(
    const float* __restrict__ in, __nv_bfloat16* __restrict__ hi,
    __nv_bfloat16* __restrict__ lo, int Kdim, int Ndim)
{
    __shared__ float t[32][33];
    const int x = blockIdx.x * 32 + threadIdx.x;
    const int ybase = blockIdx.y * 32;
#pragma unroll
    for (int j = 0; j < 32; j += 8)
        t[threadIdx.y + j][threadIdx.x] = in[(size_t)(ybase + threadIdx.y + j) * Ndim + x];
    __syncthreads();
    const int ox = ybase + threadIdx.x;
    const int oyb = blockIdx.x * 32;
#pragma unroll
    for (int j = 0; j < 32; j += 8) {
        float v = t[threadIdx.x][threadIdx.y + j];
        __nv_bfloat16 h = __float2bfloat16(v);
        size_t idx = (size_t)(oyb + threadIdx.y + j) * Kdim + ox;
        hi[idx] = h;
        lo[idx] = __float2bfloat16(v - __bfloat162float(h));
    }
}

// ---------------------------------------------------------------------------
// Causal flash attention (fp32), validated in R1.
// ---------------------------------------------------------------------------
__global__ __launch_bounds__(128) void flash_kernel(
    const float* __restrict__ Q, const float* __restrict__ K,
    const float* __restrict__ V, float* __restrict__ O)
{
    __shared__ float sQ[32][68];
    __shared__ float sKt[64][36];
    __shared__ float sV[32][128];
    __shared__ float sS[32][33];

    const int qt = blockIdx.x, h = blockIdx.y, b = blockIdx.z;
    const int tid = threadIdx.x;
    const int q0 = qt * 32;

    const float* Qb = Q + (size_t)(b * 1024 + q0) * 1024 + h * 64;
    const float* Kb = K + (size_t)(b * 1024) * 1024 + h * 64;
    const float* Vb = V + (size_t)(b * 1024) * 2048 + h * 128;

    for (int i = tid; i < 512; i += 128) {
        int r = i >> 4, c4 = i & 15;
        *(float4*)(&sQ[r][c4 * 4]) = *(const float4*)(Qb + (size_t)r * 1024 + c4 * 4);
    }

    const int row = tid >> 2;
    const int cg  = tid & 3;

    float acc[8][4];
#pragma unroll
    for (int i = 0; i < 8; i++)
#pragma unroll
        for (int j = 0; j < 4; j++) acc[i][j] = 0.f;
    float m = -INFINITY, l = 0.f;

    for (int kt = 0; kt <= qt; kt++) {
        __syncthreads();
        const int kbase = kt * 32;
        for (int i = tid; i < 512; i += 128) {
            int r = i >> 4, c4 = i & 15;
            float4 t = *(const float4*)(Kb + (size_t)(kbase + r) * 1024 + c4 * 4);
            sKt[c4 * 4 + 0][r] = t.x;
            sKt[c4 * 4 + 1][r] = t.y;
            sKt[c4 * 4 + 2][r] = t.z;
            sKt[c4 * 4 + 3][r] = t.w;
        }
        for (int i = tid; i < 1024; i += 128) {
            int r = i >> 5, c4 = i & 31;
            *(float4*)(&sV[r][c4 * 4]) = *(const float4*)(Vb + (size_t)(kbase + r) * 2048 + c4 * 4);
        }
        __syncthreads();

        {
            const int rg = tid >> 3;
            const int cgc = tid & 7;
            float s00 = 0, s01 = 0, s02 = 0, s03 = 0;
            float s10 = 0, s11 = 0, s12 = 0, s13 = 0;
#pragma unroll 8
            for (int kk = 0; kk < 64; kk++) {
                float qa = sQ[rg * 2 + 0][kk];
                float qb = sQ[rg * 2 + 1][kk];
                float4 kv = *(const float4*)(&sKt[kk][cgc * 4]);
                s00 += qa * kv.x; s01 += qa * kv.y; s02 += qa * kv.z; s03 += qa * kv.w;
                s10 += qb * kv.x; s11 += qb * kv.y; s12 += qb * kv.z; s13 += qb * kv.w;
            }
            const float sc = 0.125f;
            float vals[2][4] = {{s00, s01, s02, s03}, {s10, s11, s12, s13}};
#pragma unroll
            for (int i = 0; i < 2; i++)
#pragma unroll
                for (int j = 0; j < 4; j++) {
                    int gr = q0 + rg * 2 + i;
                    int gc = kbase + cgc * 4 + j;
                    sS[rg * 2 + i][cgc * 4 + j] = (gc <= gr) ? vals[i][j] * sc : -INFINITY;
                }
        }
        __syncthreads();

        float tmax = -INFINITY;
#pragma unroll
        for (int j = 0; j < 32; j++) tmax = fmaxf(tmax, sS[row][j]);
        float mnew = fmaxf(m, tmax);
        float alpha = __expf(m - mnew);
        __syncthreads();
#pragma unroll
        for (int j = cg; j < 32; j += 4)
            sS[row][j] = __expf(sS[row][j] - mnew);
        __syncthreads();
        float rowsum = 0.f;
#pragma unroll
        for (int j = 0; j < 32; j++) rowsum += sS[row][j];
        l = alpha * l + rowsum;
        m = mnew;
#pragma unroll
        for (int i = 0; i < 8; i++) {
            acc[i][0] *= alpha; acc[i][1] *= alpha;
            acc[i][2] *= alpha; acc[i][3] *= alpha;
        }
        for (int j = 0; j < 32; j++) {
            float p = sS[row][j];
#pragma unroll
            for (int ii = 0; ii < 8; ii++) {
                float4 vv = *(const float4*)(&sV[j][(cg + ii * 4) * 4]);
                acc[ii][0] += p * vv.x; acc[ii][1] += p * vv.y;
                acc[ii][2] += p * vv.z; acc[ii][3] += p * vv.w;
            }
        }
    }

    float inv = 1.f / l;
    float* Ob = O + (size_t)(b * 1024 + q0 + row) * 2048 + h * 128;
#pragma unroll
    for (int ii = 0; ii < 8; ii++) {
        float4 t = make_float4(acc[ii][0] * inv, acc[ii][1] * inv,
                               acc[ii][2] * inv, acc[ii][3] * inv);
        *(float4*)(Ob + (cg + ii * 4) * 4) = t;
    }
}

// ---------------------------------------------------------------------------
// Combine: z = y1 - lam_h*y2, subLN over 128, * (1-lambda_init).
// ---------------------------------------------------------------------------
__global__ __launch_bounds__(512) void combine_kernel(
    const float* __restrict__ y1, const float* __restrict__ y2,
    const float* __restrict__ lq1, const float* __restrict__ lk1,
    const float* __restrict__ lq2, const float* __restrict__ lk2,
    float* __restrict__ out)
{
    const int rowidx = blockIdx.x;
    const int h = threadIdx.x >> 5;
    const int lane = threadIdx.x & 31;

    float s1 = lq1[h * 64 + lane] * lk1[h * 64 + lane]
             + lq1[h * 64 + 32 + lane] * lk1[h * 64 + 32 + lane];
    float s2 = lq2[h * 64 + lane] * lk2[h * 64 + lane]
             + lq2[h * 64 + 32 + lane] * lk2[h * 64 + 32 + lane];
#pragma unroll
    for (int o = 16; o > 0; o >>= 1) {
        s1 += __shfl_xor_sync(0xFFFFFFFFu, s1, o);
        s2 += __shfl_xor_sync(0xFFFFFFFFu, s2, o);
    }
    const float lam = __expf(s1) - __expf(s2) + LAMBDA_INIT;

    const size_t base = (size_t)rowidx * 2048 + h * 128 + lane * 4;
    float4 a = *(const float4*)(y1 + base);
    float4 b = *(const float4*)(y2 + base);
    float z0 = a.x - lam * b.x, z1 = a.y - lam * b.y;
    float z2 = a.z - lam * b.z, z3 = a.w - lam * b.w;

    float ssum = z0 + z1 + z2 + z3;
#pragma unroll
    for (int o = 16; o > 0; o >>= 1) ssum += __shfl_xor_sync(0xFFFFFFFFu, ssum, o);
    const float mu = ssum * (1.f / 128.f);

    float d0 = z0 - mu, d1 = z1 - mu, d2 = z2 - mu, d3 = z3 - mu;
    float vs = d0 * d0 + d1 * d1 + d2 * d2 + d3 * d3;
#pragma unroll
    for (int o = 16; o > 0; o >>= 1) vs += __shfl_xor_sync(0xFFFFFFFFu, vs, o);
    const float var = vs * (1.f / 128.f);

    const float r = rsqrtf(var + 1e-5f) * (1.f - LAMBDA_INIT);
    float4 o4 = make_float4(d0 * r, d1 * r, d2 * r, d3 * r);
    *(float4*)(out + base) = o4;
}

// ---------------------------------------------------------------------------
// Host
// ---------------------------------------------------------------------------
extern "C" void kernel_launch(void* const* d_in, const int* in_sizes, int n_in,
                              void* d_out, int out_size)
{
    const float* x   = (const float*)d_in[0];
    const float* Wq1 = (const float*)d_in[1];
    const float* Wq2 = (const float*)d_in[2];
    const float* Wk1 = (const float*)d_in[3];
    const float* Wk2 = (const float*)d_in[4];
    const float* Wv  = (const float*)d_in[5];
    const float* Wc  = (const float*)d_in[6];
    const float* lq1 = (const float*)d_in[7];
    const float* lk1 = (const float*)d_in[8];
    const float* lq2 = (const float*)d_in[9];
    const float* lk2 = (const float*)d_in[10];

    float *q1, *q2, *k1, *k2, *v, *y1, *y2, *yc;
    cudaGetSymbolAddress((void**)&q1, g_q1);
    cudaGetSymbolAddress((void**)&q2, g_q2);
    cudaGetSymbolAddress((void**)&k1, g_k1);
    cudaGetSymbolAddress((void**)&k2, g_k2);
    cudaGetSymbolAddress((void**)&v,  g_v);
    cudaGetSymbolAddress((void**)&y1, g_y1);
    cudaGetSymbolAddress((void**)&y2, g_y2);
    cudaGetSymbolAddress((void**)&yc, g_yc);

    __nv_bfloat16 *xh, *xl, *ych, *ycl;
    __nv_bfloat16 *w1h, *w1l, *w2h, *w2l, *w3h, *w3l, *w4h, *w4l;
    __nv_bfloat16 *wvh, *wvl, *wch, *wcl;
    cudaGetSymbolAddress((void**)&xh,  g_xh);  cudaGetSymbolAddress((void**)&xl,  g_xl);
    cudaGetSymbolAddress((void**)&ych, g_ych); cudaGetSymbolAddress((void**)&ycl, g_ycl);
    cudaGetSymbolAddress((void**)&w1h, g_w1h); cudaGetSymbolAddress((void**)&w1l, g_w1l);
    cudaGetSymbolAddress((void**)&w2h, g_w2h); cudaGetSymbolAddress((void**)&w2l, g_w2l);
    cudaGetSymbolAddress((void**)&w3h, g_w3h); cudaGetSymbolAddress((void**)&w3l, g_w3l);
    cudaGetSymbolAddress((void**)&w4h, g_w4h); cudaGetSymbolAddress((void**)&w4l, g_w4l);
    cudaGetSymbolAddress((void**)&wvh, g_wvh); cudaGetSymbolAddress((void**)&wvl, g_wvl);
    cudaGetSymbolAddress((void**)&wch, g_wch); cudaGetSymbolAddress((void**)&wcl, g_wcl);

    cudaFuncSetAttribute(gemm_mma_kernel,
                         cudaFuncAttributeMaxDynamicSharedMemorySize, GSMEM);

    // splits: x -> (xh, xl); weights -> transposed (hi, lo) [N,K]
    split_kernel<<<4096, 256>>>((const float4*)x, xh, xl, 4096 * 1024 / 4);
    splitT_kernel<<<dim3(32, 32), dim3(32, 8)>>>(Wq1, w1h, w1l, 1024, 1024);
    splitT_kernel<<<dim3(32, 32), dim3(32, 8)>>>(Wq2, w2h, w2l, 1024, 1024);
    splitT_kernel<<<dim3(32, 32), dim3(32, 8)>>>(Wk1, w3h, w3l, 1024, 1024);
    splitT_kernel<<<dim3(32, 32), dim3(32, 8)>>>(Wk2, w4h, w4l, 1024, 1024);
    splitT_kernel<<<dim3(64, 32), dim3(32, 8)>>>(Wv,  wvh, wvl, 1024, 2048);
    splitT_kernel<<<dim3(32, 64), dim3(32, 8)>>>(Wc,  wch, wcl, 2048, 1024);

    // projections (tensor cores)
    gemm_mma_kernel<<<dim3(8, 32),  256, GSMEM>>>(xh, xl, w1h, w1l, q1, 1024, 1024);
    gemm_mma_kernel<<<dim3(8, 32),  256, GSMEM>>>(xh, xl, w2h, w2l, q2, 1024, 1024);
    gemm_mma_kernel<<<dim3(8, 32),  256, GSMEM>>>(xh, xl, w3h, w3l, k1, 1024, 1024);
    gemm_mma_kernel<<<dim3(8, 32),  256, GSMEM>>>(xh, xl, w4h, w4l, k2, 1024, 1024);
    gemm_mma_kernel<<<dim3(16, 32), 256, GSMEM>>>(xh, xl, wvh, wvl, v,  1024, 2048);

    // dual flash attention streams
    dim3 gF(1024 / 32, 16, 4);
    flash_kernel<<<gF, 128>>>(q1, k1, v, y1);
    flash_kernel<<<gF, 128>>>(q2, k2, v, y2);

    // combine + subLN
    combine_kernel<<<4096, 512>>>(y1, y2, lq1, lk1, lq2, lk2, yc);

    // output projection
    split_kernel<<<8192, 256>>>((const float4*)yc, ych, ycl, 4096 * 2048 / 4);
    gemm_mma_kernel<<<dim3(8, 32), 256, GSMEM>>>(ych, ycl, wch, wcl,
                                                 (float*)d_out, 2048, 1024);
}

// round 6
// speedup vs baseline: 3.4300x; 2.3913x over previous
#include <cuda_runtime.h>
#include <cuda_bf16.h>
#include <stdint.h>
#include <math.h>

// ---------------------------------------------------------------------------
// MultiHeadDiffAttention  (B=4, T=1024, C=1024, H=16, hs=64, dv=128)
// R4: GEMMs on mma.sync (split-bf16, direct split output) + flash attention
//     on mma.sync (split Q/K/P/V, register softmax). fp32 only at y1/y2/out.
// ---------------------------------------------------------------------------

#define LAMBDA_INIT 0.3555090675909693f   // 0.8 - 0.6*exp(-0.3)

// fp32 intermediates
static __device__ float g_y1[4096 * 2048];
static __device__ float g_y2[4096 * 2048];

// split-bf16 activations
static __device__ __align__(16) __nv_bfloat16 g_xh[4096 * 1024],  g_xl[4096 * 1024];
static __device__ __align__(16) __nv_bfloat16 g_q1h[4096 * 1024], g_q1l[4096 * 1024];
static __device__ __align__(16) __nv_bfloat16 g_q2h[4096 * 1024], g_q2l[4096 * 1024];
static __device__ __align__(16) __nv_bfloat16 g_k1h[4096 * 1024], g_k1l[4096 * 1024];
static __device__ __align__(16) __nv_bfloat16 g_k2h[4096 * 1024], g_k2l[4096 * 1024];
static __device__ __align__(16) __nv_bfloat16 g_vh[4096 * 2048],  g_vl[4096 * 2048];
static __device__ __align__(16) __nv_bfloat16 g_ych[4096 * 2048], g_ycl[4096 * 2048];
// split-bf16 weights, transposed to [N,K]
static __device__ __align__(16) __nv_bfloat16 g_w1h[1024 * 1024], g_w1l[1024 * 1024];
static __device__ __align__(16) __nv_bfloat16 g_w2h[1024 * 1024], g_w2l[1024 * 1024];
static __device__ __align__(16) __nv_bfloat16 g_w3h[1024 * 1024], g_w3l[1024 * 1024];
static __device__ __align__(16) __nv_bfloat16 g_w4h[1024 * 1024], g_w4l[1024 * 1024];
static __device__ __align__(16) __nv_bfloat16 g_wvh[2048 * 1024], g_wvl[2048 * 1024];
static __device__ __align__(16) __nv_bfloat16 g_wch[1024 * 2048], g_wcl[1024 * 2048];

// ---------------------------------------------------------------------------
// helpers
// ---------------------------------------------------------------------------
__device__ __forceinline__ uint32_t smem_u32(const void* p) {
    uint32_t a;
    asm("{ .reg .u64 t; cvta.to.shared.u64 t, %1; cvt.u32.u64 %0, t; }" : "=r"(a) : "l"(p));
    return a;
}
__device__ __forceinline__ void cp16(uint32_t saddr, const void* g) {
    asm volatile("cp.async.cg.shared.global [%0], [%1], 16;" :: "r"(saddr), "l"(g) : "memory");
}
__device__ __forceinline__ void cp_commit() {
    asm volatile("cp.async.commit_group;" ::: "memory");
}
__device__ __forceinline__ void ldsm4(uint32_t* r, uint32_t addr) {
    asm volatile("ldmatrix.sync.aligned.m8n8.x4.shared.b16 {%0,%1,%2,%3}, [%4];"
                 : "=r"(r[0]), "=r"(r[1]), "=r"(r[2]), "=r"(r[3]) : "r"(addr));
}
__device__ __forceinline__ void ldsm4t(uint32_t* r, uint32_t addr) {
    asm volatile("ldmatrix.sync.aligned.m8n8.x4.trans.shared.b16 {%0,%1,%2,%3}, [%4];"
                 : "=r"(r[0]), "=r"(r[1]), "=r"(r[2]), "=r"(r[3]) : "r"(addr));
}
__device__ __forceinline__ void mma_bf16(float* d, const uint32_t* a, const uint32_t* b) {
    asm volatile(
        "mma.sync.aligned.m16n8k16.row.col.f32.bf16.bf16.f32 "
        "{%0,%1,%2,%3}, {%4,%5,%6,%7}, {%8,%9}, {%0,%1,%2,%3};"
        : "+f"(d[0]), "+f"(d[1]), "+f"(d[2]), "+f"(d[3])
        : "r"(a[0]), "r"(a[1]), "r"(a[2]), "r"(a[3]), "r"(b[0]), "r"(b[1]));
}
__device__ __forceinline__ uint32_t pack_bf16(float x, float y) {
    __nv_bfloat162 t = __floats2bfloat162_rn(x, y);
    return *(uint32_t*)&t;
}

// ---------------------------------------------------------------------------
// Split-bf16 tensor-core GEMM: C[M,N] = A[M,K] @ B[N,K]^T
// SPLIT_OUT=0: fp32 C.  SPLIT_OUT=1: (hi,lo) bf16 output.
// ---------------------------------------------------------------------------
#define GBM 128
#define GBN 128
#define GBK 32
#define GTILE_B (GBM * GBK * 2)
#define GSTAGE_B (4 * GTILE_B)
#define GSTAGES 3
#define GSMEM (GSTAGES * GSTAGE_B)

template<int SPLIT_OUT>
__global__ __launch_bounds__(256, 1) void gemm_mma_kernel(
    const __nv_bfloat16* __restrict__ Ah, const __nv_bfloat16* __restrict__ Al,
    const __nv_bfloat16* __restrict__ Bh, const __nv_bfloat16* __restrict__ Bl,
    float* __restrict__ C, __nv_bfloat16* __restrict__ OH, __nv_bfloat16* __restrict__ OL,
    int K, int N)
{
    extern __shared__ char smem[];
    const uint32_t sb = smem_u32(smem);
    const int tid = threadIdx.x;
    const int wid = tid >> 5, lane = tid & 31;
    const int m0 = blockIdx.y * GBM, n0 = blockIdx.x * GBN;
    const int wm = (wid & 1) * 64, wn = (wid >> 1) * 32;
    const int nk = K / GBK;

    float acc[4][4][4];
#pragma unroll
    for (int i = 0; i < 4; i++)
#pragma unroll
        for (int j = 0; j < 4; j++)
#pragma unroll
            for (int r = 0; r < 4; r++) acc[i][j][r] = 0.f;

    const int ch0_row = tid >> 2, ch0_c = tid & 3;
    const int ch1_row = (tid + 256) >> 2, ch1_c = tid & 3;
    const uint32_t so0 = ch0_row * 64 + ((ch0_c ^ ((ch0_row >> 1) & 3)) * 16);
    const uint32_t so1 = ch1_row * 64 + ((ch1_c ^ ((ch1_row >> 1) & 3)) * 16);

#define LOAD_STAGE(kt, s)                                                          \
    do {                                                                           \
        const uint32_t sbase = sb + (s) * GSTAGE_B;                                \
        const int k0 = (kt) * GBK;                                                 \
        cp16(sbase + 0 * GTILE_B + so0, Ah + (size_t)(m0 + ch0_row) * K + k0 + ch0_c * 8); \
        cp16(sbase + 0 * GTILE_B + so1, Ah + (size_t)(m0 + ch1_row) * K + k0 + ch1_c * 8); \
        cp16(sbase + 1 * GTILE_B + so0, Al + (size_t)(m0 + ch0_row) * K + k0 + ch0_c * 8); \
        cp16(sbase + 1 * GTILE_B + so1, Al + (size_t)(m0 + ch1_row) * K + k0 + ch1_c * 8); \
        cp16(sbase + 2 * GTILE_B + so0, Bh + (size_t)(n0 + ch0_row) * K + k0 + ch0_c * 8); \
        cp16(sbase + 2 * GTILE_B + so1, Bh + (size_t)(n0 + ch1_row) * K + k0 + ch1_c * 8); \
        cp16(sbase + 3 * GTILE_B + so0, Bl + (size_t)(n0 + ch0_row) * K + k0 + ch0_c * 8); \
        cp16(sbase + 3 * GTILE_B + so1, Bl + (size_t)(n0 + ch1_row) * K + k0 + ch1_c * 8); \
    } while (0)

    LOAD_STAGE(0, 0); cp_commit();
    LOAD_STAGE(1, 1); cp_commit();

    const int a_row_in_tile = lane & 15;
    const int a_chunk_add   = lane >> 4;
    const int b_row_in_tile = (lane & 7) + ((lane >> 4) << 3);
    const int b_chunk_add   = (lane >> 3) & 1;

    int stage = 0;
    for (int kt = 0; kt < nk; kt++) {
        if (kt + 2 < nk) LOAD_STAGE(kt + 2, (kt + 2) % GSTAGES);
        cp_commit();
        asm volatile("cp.async.wait_group 2;" ::: "memory");
        __syncthreads();

        const uint32_t sA_h = sb + stage * GSTAGE_B;
        const uint32_t sA_l = sA_h + GTILE_B;
        const uint32_t sB_h = sA_h + 2 * GTILE_B;
        const uint32_t sB_l = sA_h + 3 * GTILE_B;

#pragma unroll
        for (int ks = 0; ks < 2; ks++) {
            uint32_t ah[4][4], al[4][4], bh[2][4], bl[2][4];
#pragma unroll
            for (int tm = 0; tm < 4; tm++) {
                const int row = wm + tm * 16 + a_row_in_tile;
                const int chunk = ks * 2 + a_chunk_add;
                const uint32_t off = row * 64 + ((chunk ^ ((row >> 1) & 3)) * 16);
                ldsm4(ah[tm], sA_h + off);
                ldsm4(al[tm], sA_l + off);
            }
#pragma unroll
            for (int tp = 0; tp < 2; tp++) {
                const int row = wn + tp * 16 + b_row_in_tile;
                const int chunk = ks * 2 + b_chunk_add;
                const uint32_t off = row * 64 + ((chunk ^ ((row >> 1) & 3)) * 16);
                ldsm4(bh[tp], sB_h + off);
                ldsm4(bl[tp], sB_l + off);
            }
#pragma unroll
            for (int tm = 0; tm < 4; tm++)
#pragma unroll
                for (int tn = 0; tn < 4; tn++) {
                    const int p = tn >> 1, hh = (tn & 1) * 2;
                    mma_bf16(acc[tm][tn], ah[tm], &bh[p][hh]);
                    mma_bf16(acc[tm][tn], ah[tm], &bl[p][hh]);
                    mma_bf16(acc[tm][tn], al[tm], &bh[p][hh]);
                }
        }
        __syncthreads();
        stage = (stage + 1) % GSTAGES;
    }

    const int g = lane >> 2, cq = lane & 3;
#pragma unroll
    for (int tm = 0; tm < 4; tm++)
#pragma unroll
        for (int tn = 0; tn < 4; tn++) {
            const int row = m0 + wm + tm * 16 + g;
            const int col = n0 + wn + tn * 8 + cq * 2;
            if (SPLIT_OUT) {
#pragma unroll
                for (int rr = 0; rr < 2; rr++) {
                    float v0 = acc[tm][tn][rr * 2 + 0], v1 = acc[tm][tn][rr * 2 + 1];
                    __nv_bfloat16 h0 = __float2bfloat16(v0), h1 = __float2bfloat16(v1);
                    float l0 = v0 - __bfloat162float(h0), l1 = v1 - __bfloat162float(h1);
                    size_t idx = (size_t)(row + rr * 8) * N + col;
                    *(__nv_bfloat162*)&OH[idx] = __nv_bfloat162(h0, h1);
                    *(__nv_bfloat162*)&OL[idx] = __nv_bfloat162(__float2bfloat16(l0),
                                                                __float2bfloat16(l1));
                }
            } else {
                *(float2*)&C[(size_t)row * N + col] =
                    make_float2(acc[tm][tn][0], acc[tm][tn][1]);
                *(float2*)&C[(size_t)(row + 8) * N + col] =
                    make_float2(acc[tm][tn][2], acc[tm][tn][3]);
            }
        }
#undef LOAD_STAGE
}

// ---------------------------------------------------------------------------
// fp32 -> (hi, lo) bf16 split, contiguous (for x only)
// ---------------------------------------------------------------------------
__global__ __launch_bounds__(256) void split_kernel(
    const float4* __restrict__ in, __nv_bfloat16* __restrict__ hi,
    __nv_bfloat16* __restrict__ lo, int n4)
{
    int i = blockIdx.x * blockDim.x + threadIdx.x;
    if (i >= n4) return;
    float4 v = in[i];
    __nv_bfloat16 h0 = __float2bfloat16(v.x), h1 = __float2bfloat16(v.y);
    __nv_bfloat16 h2 = __float2bfloat16(v.z), h3 = __float2bfloat16(v.w);
    __nv_bfloat162* H = (__nv_bfloat162*)hi + 2 * i;
    __nv_bfloat162* L = (__nv_bfloat162*)lo + 2 * i;
    H[0] = __nv_bfloat162(h0, h1);
    H[1] = __nv_bfloat162(h2, h3);
    L[0] = __nv_bfloat162(__float2bfloat16(v.x - __bfloat162float(h0)),
                          __float2bfloat16(v.y - __bfloat162float(h1)));
    L[1] = __nv_bfloat162(__float2bfloat16(v.z - __bfloat162float(h2)),
                          __float2bfloat16(v.w - __bfloat162float(h3)));
}

// ---------------------------------------------------------------------------
// fp32 [K,N] -> transposed (hi, lo) bf16 [N,K]
// ---------------------------------------------------------------------------
__global__ __launch_bounds__(256) void splitT_kernel(
    const float* __restrict__ in, __nv_bfloat16* __restrict__ hi,
    __nv_bfloat16* __restrict__ lo, int Kdim, int Ndim)
{
    __shared__ float t[32][33];
    const int x = blockIdx.x * 32 + threadIdx.x;
    const int ybase = blockIdx.y * 32;
#pragma unroll
    for (int j = 0; j < 32; j += 8)
        t[threadIdx.y + j][threadIdx.x] = in[(size_t)(ybase + threadIdx.y + j) * Ndim + x];
    __syncthreads();
    const int ox = ybase + threadIdx.x;
    const int oyb = blockIdx.x * 32;
#pragma unroll
    for (int j = 0; j < 32; j += 8) {
        float v = t[threadIdx.x][threadIdx.y + j];
        __nv_bfloat16 h = __float2bfloat16(v);
        size_t idx = (size_t)(oyb + threadIdx.y + j) * Kdim + ox;
        hi[idx] = h;
        lo[idx] = __float2bfloat16(v - __bfloat162float(h));
    }
}

// ---------------------------------------------------------------------------
// Tensor-core causal flash attention, one softmax stream.
// Q,K split bf16 [4096,1024] (head h at cols h*64); V split bf16 [4096,2048]
// (head h at cols h*128). O fp32 [4096,2048]. Br=Bc=64, 4 warps.
// ---------------------------------------------------------------------------
#define FQH 0
#define FQL 9216
#define FSTAGE0 18432
#define FSTAGE_B 53248           // KH 9216 | KL 9216 | VH 17408 | VL 17408
#define FKH 0
#define FKL 9216
#define FVH 18432
#define FVL 35840
#define FSMEM (FSTAGE0 + 2 * FSTAGE_B)   // 124928

__global__ __launch_bounds__(128) void flash_mma_kernel(
    const __nv_bfloat16* __restrict__ Qh, const __nv_bfloat16* __restrict__ Ql,
    const __nv_bfloat16* __restrict__ Kh, const __nv_bfloat16* __restrict__ Kl,
    const __nv_bfloat16* __restrict__ Vh, const __nv_bfloat16* __restrict__ Vl,
    float* __restrict__ O)
{
    extern __shared__ char smem[];
    const uint32_t sb = smem_u32(smem);
    const int qt = blockIdx.x, h = blockIdx.y, b = blockIdx.z;
    const int tid = threadIdx.x, wid = tid >> 5, lane = tid & 31;
    const int q0 = qt * 64, wm = wid * 16;
    const int g = lane >> 2;

    // ---- load Q tile (64x64 h + l) ----
    {
        const size_t qbase = (size_t)(b * 1024 + q0) * 1024 + h * 64;
#pragma unroll
        for (int i = 0; i < 4; i++) {
            int c = tid + i * 128;
            int row = c >> 3, ch = c & 7;
            cp16(sb + FQH + row * 144 + ch * 16, Qh + qbase + (size_t)row * 1024 + ch * 8);
            cp16(sb + FQL + row * 144 + ch * 16, Ql + qbase + (size_t)row * 1024 + ch * 8);
        }
    }

#define LOAD_KV(kt, s)                                                                  \
    do {                                                                                \
        const uint32_t base = sb + FSTAGE0 + (s) * FSTAGE_B;                            \
        const size_t kgb = (size_t)(b * 1024 + (kt) * 64) * 1024 + h * 64;              \
        const size_t vgb = (size_t)(b * 1024 + (kt) * 64) * 2048 + h * 128;             \
        _Pragma("unroll")                                                               \
        for (int i = 0; i < 4; i++) {                                                   \
            int c = tid + i * 128;                                                      \
            int row = c >> 3, ch = c & 7;                                               \
            cp16(base + FKH + row * 144 + ch * 16, Kh + kgb + (size_t)row * 1024 + ch * 8); \
            cp16(base + FKL + row * 144 + ch * 16, Kl + kgb + (size_t)row * 1024 + ch * 8); \
        }                                                                               \
        _Pragma("unroll")                                                               \
        for (int i = 0; i < 8; i++) {                                                   \
            int c = tid + i * 128;                                                      \
            int row = c >> 4, ch = c & 15;                                              \
            cp16(base + FVH + row * 272 + ch * 16, Vh + vgb + (size_t)row * 2048 + ch * 8); \
            cp16(base + FVL + row * 272 + ch * 16, Vl + vgb + (size_t)row * 2048 + ch * 8); \
        }                                                                               \
    } while (0)

    LOAD_KV(0, 0);
    cp_commit();

    float Oa[16][4];
#pragma unroll
    for (int n = 0; n < 16; n++)
#pragma unroll
        for (int r = 0; r < 4; r++) Oa[n][r] = 0.f;
    float m_a = -1e30f, m_b = -1e30f, l_a = 0.f, l_b = 0.f;
    uint32_t qfh[4][4], qfl[4][4];

    const int brow = (lane & 7) + ((lane >> 4) << 3);
    const int bchunk = (lane >> 3) & 1;
    const int rowa = q0 + wm + g, rowb = rowa + 8;

    for (int kt = 0; kt <= qt; kt++) {
        if (kt < qt) LOAD_KV(kt + 1, (kt + 1) & 1);
        cp_commit();
        asm volatile("cp.async.wait_group 1;" ::: "memory");
        __syncthreads();

        if (kt == 0) {
#pragma unroll
            for (int s = 0; s < 4; s++) {
                const uint32_t off = (wm + (lane & 15)) * 144 + (s * 2 + (lane >> 4)) * 16;
                ldsm4(qfh[s], sb + FQH + off);
                ldsm4(qfl[s], sb + FQL + off);
            }
        }

        const uint32_t kbh = sb + FSTAGE0 + (kt & 1) * FSTAGE_B + FKH;
        const uint32_t kbl = kbh + (FKL - FKH);
        const uint32_t vbh = sb + FSTAGE0 + (kt & 1) * FSTAGE_B + FVH;
        const uint32_t vbl = vbh + (FVL - FVH);

        // ---- S = Q K^T (split, 3 terms) ----
        float S[8][4];
#pragma unroll
        for (int j = 0; j < 8; j++)
#pragma unroll
            for (int r = 0; r < 4; r++) S[j][r] = 0.f;
#pragma unroll
        for (int jj = 0; jj < 4; jj++)
#pragma unroll
            for (int s = 0; s < 4; s++) {
                uint32_t kh4[4], kl4[4];
                const uint32_t off = (16 * jj + brow) * 144 + (s * 2 + bchunk) * 16;
                ldsm4(kh4, kbh + off);
                ldsm4(kl4, kbl + off);
                mma_bf16(S[2 * jj],     qfh[s], kh4);
                mma_bf16(S[2 * jj],     qfh[s], kl4);
                mma_bf16(S[2 * jj],     qfl[s], kh4);
                mma_bf16(S[2 * jj + 1], qfh[s], kh4 + 2);
                mma_bf16(S[2 * jj + 1], qfh[s], kl4 + 2);
                mma_bf16(S[2 * jj + 1], qfl[s], kh4 + 2);
            }

        // ---- scale + causal mask ----
        const float sc = 0.125f;
        if (kt == qt) {
#pragma unroll
            for (int j = 0; j < 8; j++) {
                const int col = kt * 64 + j * 8 + (lane & 3) * 2;
                S[j][0] = (col     <= rowa) ? S[j][0] * sc : -1e30f;
                S[j][1] = (col + 1 <= rowa) ? S[j][1] * sc : -1e30f;
                S[j][2] = (col     <= rowb) ? S[j][2] * sc : -1e30f;
                S[j][3] = (col + 1 <= rowb) ? S[j][3] * sc : -1e30f;
            }
        } else {
#pragma unroll
            for (int j = 0; j < 8; j++)
#pragma unroll
                for (int r = 0; r < 4; r++) S[j][r] *= sc;
        }

        // ---- online softmax (register, quad-reduced) ----
        float mxa = -1e30f, mxb = -1e30f;
#pragma unroll
        for (int j = 0; j < 8; j++) {
            mxa = fmaxf(mxa, fmaxf(S[j][0], S[j][1]));
            mxb = fmaxf(mxb, fmaxf(S[j][2], S[j][3]));
        }
        mxa = fmaxf(mxa, __shfl_xor_sync(0xFFFFFFFFu, mxa, 1));
        mxa = fmaxf(mxa, __shfl_xor_sync(0xFFFFFFFFu, mxa, 2));
        mxb = fmaxf(mxb, __shfl_xor_sync(0xFFFFFFFFu, mxb, 1));
        mxb = fmaxf(mxb, __shfl_xor_sync(0xFFFFFFFFu, mxb, 2));
        const float mna = fmaxf(m_a, mxa), mnb = fmaxf(m_b, mxb);
        const float alpha_a = __expf(m_a - mna), alpha_b = __expf(m_b - mnb);
        float suma = 0.f, sumb = 0.f;
#pragma unroll
        for (int j = 0; j < 8; j++) {
            S[j][0] = __expf(S[j][0] - mna);
            S[j][1] = __expf(S[j][1] - mna);
            S[j][2] = __expf(S[j][2] - mnb);
            S[j][3] = __expf(S[j][3] - mnb);
            suma += S[j][0] + S[j][1];
            sumb += S[j][2] + S[j][3];
        }
        suma += __shfl_xor_sync(0xFFFFFFFFu, suma, 1);
        suma += __shfl_xor_sync(0xFFFFFFFFu, suma, 2);
        sumb += __shfl_xor_sync(0xFFFFFFFFu, sumb, 1);
        sumb += __shfl_xor_sync(0xFFFFFFFFu, sumb, 2);
        l_a = alpha_a * l_a + suma;
        l_b = alpha_b * l_b + sumb;
        m_a = mna; m_b = mnb;
#pragma unroll
        for (int n = 0; n < 16; n++) {
            Oa[n][0] *= alpha_a; Oa[n][1] *= alpha_a;
            Oa[n][2] *= alpha_b; Oa[n][3] *= alpha_b;
        }

        // ---- P -> split bf16 A-frags ----
        uint32_t ph[4][4], pl[4][4];
#pragma unroll
        for (int jj = 0; jj < 4; jj++) {
            const float* s0 = S[2 * jj];
            const float* s1 = S[2 * jj + 1];
            float r[8];
#pragma unroll
            for (int e = 0; e < 4; e++) {
                r[e]     = s0[e] - __bfloat162float(__float2bfloat16(s0[e]));
                r[4 + e] = s1[e] - __bfloat162float(__float2bfloat16(s1[e]));
            }
            ph[jj][0] = pack_bf16(s0[0], s0[1]);
            ph[jj][1] = pack_bf16(s0[2], s0[3]);
            ph[jj][2] = pack_bf16(s1[0], s1[1]);
            ph[jj][3] = pack_bf16(s1[2], s1[3]);
            pl[jj][0] = pack_bf16(r[0], r[1]);
            pl[jj][1] = pack_bf16(r[2], r[3]);
            pl[jj][2] = pack_bf16(r[4], r[5]);
            pl[jj][3] = pack_bf16(r[6], r[7]);
        }

        // ---- O += P V (split, 3 terms) ----
        const int krow_base = (lane & 7) + (((lane >> 3) & 1) << 3);
        const uint32_t cadd = (lane >> 4) * 16;
#pragma unroll
        for (int jv = 0; jv < 8; jv++)
#pragma unroll
            for (int s = 0; s < 4; s++) {
                uint32_t vh4[4], vl4[4];
                const uint32_t off = (s * 16 + krow_base) * 272 + jv * 32 + cadd;
                ldsm4t(vh4, vbh + off);
                ldsm4t(vl4, vbl + off);
                mma_bf16(Oa[2 * jv],     ph[s], vh4);
                mma_bf16(Oa[2 * jv],     ph[s], vl4);
                mma_bf16(Oa[2 * jv],     pl[s], vh4);
                mma_bf16(Oa[2 * jv + 1], ph[s], vh4 + 2);
                mma_bf16(Oa[2 * jv + 1], ph[s], vl4 + 2);
                mma_bf16(Oa[2 * jv + 1], pl[s], vh4 + 2);
            }
        __syncthreads();
    }

    // ---- epilogue ----
    const float inva = 1.f / l_a, invb = 1.f / l_b;
    float* Oba = O + (size_t)(b * 1024 + rowa) * 2048 + h * 128 + (lane & 3) * 2;
    float* Obb = O + (size_t)(b * 1024 + rowb) * 2048 + h * 128 + (lane & 3) * 2;
#pragma unroll
    for (int n = 0; n < 16; n++) {
        *(float2*)(Oba + n * 8) = make_float2(Oa[n][0] * inva, Oa[n][1] * inva);
        *(float2*)(Obb + n * 8) = make_float2(Oa[n][2] * invb, Oa[n][3] * invb);
    }
#undef LOAD_KV
}

// ---------------------------------------------------------------------------
// Combine: z = y1 - lam_h*y2, subLN over 128, * (1-lambda_init), split output.
// ---------------------------------------------------------------------------
__global__ __launch_bounds__(512) void combine_kernel(
    const float* __restrict__ y1, const float* __restrict__ y2,
    const float* __restrict__ lq1, const float* __restrict__ lk1,
    const float* __restrict__ lq2, const float* __restrict__ lk2,
    __nv_bfloat16* __restrict__ outh, __nv_bfloat16* __restrict__ outl)
{
    const int rowidx = blockIdx.x;
    const int h = threadIdx.x >> 5;
    const int lane = threadIdx.x & 31;

    float s1 = lq1[h * 64 + lane] * lk1[h * 64 + lane]
             + lq1[h * 64 + 32 + lane] * lk1[h * 64 + 32 + lane];
    float s2 = lq2[h * 64 + lane] * lk2[h * 64 + lane]
             + lq2[h * 64 + 32 + lane] * lk2[h * 64 + 32 + lane];
#pragma unroll
    for (int o = 16; o > 0; o >>= 1) {
        s1 += __shfl_xor_sync(0xFFFFFFFFu, s1, o);
        s2 += __shfl_xor_sync(0xFFFFFFFFu, s2, o);
    }
    const float lam = __expf(s1) - __expf(s2) + LAMBDA_INIT;

    const size_t base = (size_t)rowidx * 2048 + h * 128 + lane * 4;
    float4 a = *(const float4*)(y1 + base);
    float4 b = *(const float4*)(y2 + base);
    float z0 = a.x - lam * b.x, z1 = a.y - lam * b.y;
    float z2 = a.z - lam * b.z, z3 = a.w - lam * b.w;

    float ssum = z0 + z1 + z2 + z3;
#pragma unroll
    for (int o = 16; o > 0; o >>= 1) ssum += __shfl_xor_sync(0xFFFFFFFFu, ssum, o);
    const float mu = ssum * (1.f / 128.f);

    float d0 = z0 - mu, d1 = z1 - mu, d2 = z2 - mu, d3 = z3 - mu;
    float vs = d0 * d0 + d1 * d1 + d2 * d2 + d3 * d3;
#pragma unroll
    for (int o = 16; o > 0; o >>= 1) vs += __shfl_xor_sync(0xFFFFFFFFu, vs, o);
    const float var = vs * (1.f / 128.f);

    const float r = rsqrtf(var + 1e-5f) * (1.f - LAMBDA_INIT);
    float o0 = d0 * r, o1 = d1 * r, o2 = d2 * r, o3 = d3 * r;
    __nv_bfloat16 h0 = __float2bfloat16(o0), h1 = __float2bfloat16(o1);
    __nv_bfloat16 h2 = __float2bfloat16(o2), h3 = __float2bfloat16(o3);
    __nv_bfloat162* H = (__nv_bfloat162*)(outh + base);
    __nv_bfloat162* L = (__nv_bfloat162*)(outl + base);
    H[0] = __nv_bfloat162(h0, h1);
    H[1] = __nv_bfloat162(h2, h3);
    L[0] = __nv_bfloat162(__float2bfloat16(o0 - __bfloat162float(h0)),
                          __float2bfloat16(o1 - __bfloat162float(h1)));
    L[1] = __nv_bfloat162(__float2bfloat16(o2 - __bfloat162float(h2)),
                          __float2bfloat16(o3 - __bfloat162float(h3)));
}

// ---------------------------------------------------------------------------
// Host
// ---------------------------------------------------------------------------
extern "C" void kernel_launch(void* const* d_in, const int* in_sizes, int n_in,
                              void* d_out, int out_size)
{
    const float* x   = (const float*)d_in[0];
    const float* Wq1 = (const float*)d_in[1];
    const float* Wq2 = (const float*)d_in[2];
    const float* Wk1 = (const float*)d_in[3];
    const float* Wk2 = (const float*)d_in[4];
    const float* Wv  = (const float*)d_in[5];
    const float* Wc  = (const float*)d_in[6];
    const float* lq1 = (const float*)d_in[7];
    const float* lk1 = (const float*)d_in[8];
    const float* lq2 = (const float*)d_in[9];
    const float* lk2 = (const float*)d_in[10];

    float *y1, *y2;
    cudaGetSymbolAddress((void**)&y1, g_y1);
    cudaGetSymbolAddress((void**)&y2, g_y2);

    __nv_bfloat16 *xh, *xl, *q1h, *q1l, *q2h, *q2l, *k1h, *k1l, *k2h, *k2l;
    __nv_bfloat16 *vh, *vl, *ych, *ycl;
    __nv_bfloat16 *w1h, *w1l, *w2h, *w2l, *w3h, *w3l, *w4h, *w4l;
    __nv_bfloat16 *wvh, *wvl, *wch, *wcl;
    cudaGetSymbolAddress((void**)&xh,  g_xh);  cudaGetSymbolAddress((void**)&xl,  g_xl);
    cudaGetSymbolAddress((void**)&q1h, g_q1h); cudaGetSymbolAddress((void**)&q1l, g_q1l);
    cudaGetSymbolAddress((void**)&q2h, g_q2h); cudaGetSymbolAddress((void**)&q2l, g_q2l);
    cudaGetSymbolAddress((void**)&k1h, g_k1h); cudaGetSymbolAddress((void**)&k1l, g_k1l);
    cudaGetSymbolAddress((void**)&k2h, g_k2h); cudaGetSymbolAddress((void**)&k2l, g_k2l);
    cudaGetSymbolAddress((void**)&vh,  g_vh);  cudaGetSymbolAddress((void**)&vl,  g_vl);
    cudaGetSymbolAddress((void**)&ych, g_ych); cudaGetSymbolAddress((void**)&ycl, g_ycl);
    cudaGetSymbolAddress((void**)&w1h, g_w1h); cudaGetSymbolAddress((void**)&w1l, g_w1l);
    cudaGetSymbolAddress((void**)&w2h, g_w2h); cudaGetSymbolAddress((void**)&w2l, g_w2l);
    cudaGetSymbolAddress((void**)&w3h, g_w3h); cudaGetSymbolAddress((void**)&w3l, g_w3l);
    cudaGetSymbolAddress((void**)&w4h, g_w4h); cudaGetSymbolAddress((void**)&w4l, g_w4l);
    cudaGetSymbolAddress((void**)&wvh, g_wvh); cudaGetSymbolAddress((void**)&wvl, g_wvl);
    cudaGetSymbolAddress((void**)&wch, g_wch); cudaGetSymbolAddress((void**)&wcl, g_wcl);

    cudaFuncSetAttribute(gemm_mma_kernel<0>,
                         cudaFuncAttributeMaxDynamicSharedMemorySize, GSMEM);
    cudaFuncSetAttribute(gemm_mma_kernel<1>,
                         cudaFuncAttributeMaxDynamicSharedMemorySize, GSMEM);
    cudaFuncSetAttribute(flash_mma_kernel,
                         cudaFuncAttributeMaxDynamicSharedMemorySize, FSMEM);

    // splits
    split_kernel<<<4096, 256>>>((const float4*)x, xh, xl, 4096 * 1024 / 4);
    splitT_kernel<<<dim3(32, 32), dim3(32, 8)>>>(Wq1, w1h, w1l, 1024, 1024);
    splitT_kernel<<<dim3(32, 32), dim3(32, 8)>>>(Wq2, w2h, w2l, 1024, 1024);
    splitT_kernel<<<dim3(32, 32), dim3(32, 8)>>>(Wk1, w3h, w3l, 1024, 1024);
    splitT_kernel<<<dim3(32, 32), dim3(32, 8)>>>(Wk2, w4h, w4l, 1024, 1024);
    splitT_kernel<<<dim3(64, 32), dim3(32, 8)>>>(Wv,  wvh, wvl, 1024, 2048);
    splitT_kernel<<<dim3(32, 64), dim3(32, 8)>>>(Wc,  wch, wcl, 2048, 1024);

    // projections -> split bf16 outputs
    gemm_mma_kernel<1><<<dim3(8, 32),  256, GSMEM>>>(xh, xl, w1h, w1l, nullptr, q1h, q1l, 1024, 1024);
    gemm_mma_kernel<1><<<dim3(8, 32),  256, GSMEM>>>(xh, xl, w2h, w2l, nullptr, q2h, q2l, 1024, 1024);
    gemm_mma_kernel<1><<<dim3(8, 32),  256, GSMEM>>>(xh, xl, w3h, w3l, nullptr, k1h, k1l, 1024, 1024);
    gemm_mma_kernel<1><<<dim3(8, 32),  256, GSMEM>>>(xh, xl, w4h, w4l, nullptr, k2h, k2l, 1024, 1024);
    gemm_mma_kernel<1><<<dim3(16, 32), 256, GSMEM>>>(xh, xl, wvh, wvl, nullptr, vh, vl, 1024, 2048);

    // dual flash attention streams (tensor cores)
    dim3 gF(16, 16, 4);
    flash_mma_kernel<<<gF, 128, FSMEM>>>(q1h, q1l, k1h, k1l, vh, vl, y1);
    flash_mma_kernel<<<gF, 128, FSMEM>>>(q2h, q2l, k2h, k2l, vh, vl, y2);

    // combine + subLN -> split bf16
    combine_kernel<<<4096, 512>>>(y1, y2, lq1, lk1, lq2, lk2, ych, ycl);

    // output projection -> fp32 d_out
    gemm_mma_kernel<0><<<dim3(8, 32), 256, GSMEM>>>(ych, ycl, wch, wcl,
                                                    (float*)d_out, nullptr, nullptr,
                                                    2048, 1024);
}